// round 9
// baseline (speedup 1.0000x reference)
#include <cuda_runtime.h>
#include <cuda_bf16.h>
#include <math.h>
#include <cstdint>

// Problem constants
#define NN    50000
#define DEG   16
#define EDGES (NN * DEG)
#define DIM   128
#define HID   128

// ---------------------------------------------------------------------------
__device__ __forceinline__ uint32_t smem_to_u32(const void* p) {
    uint32_t a;
    asm("{ .reg .u64 t; cvta.to.shared.u64 t, %1; cvt.u32.u64 %0, t; }" : "=r"(a) : "l"(p));
    return a;
}

__device__ __forceinline__ void ldsm_x4(uint32_t (&r)[4], uint32_t addr) {
    asm volatile("ldmatrix.sync.aligned.m8n8.x4.shared.b16 {%0,%1,%2,%3}, [%4];"
                 : "=r"(r[0]), "=r"(r[1]), "=r"(r[2]), "=r"(r[3]) : "r"(addr));
}

__device__ __forceinline__ void mma16816(float (&c)[4], const uint32_t (&a)[4],
                                         uint32_t b0, uint32_t b1) {
    asm volatile("mma.sync.aligned.m16n8k16.row.col.f32.bf16.bf16.f32 "
                 "{%0,%1,%2,%3}, {%4,%5,%6,%7}, {%8,%9}, {%0,%1,%2,%3};"
                 : "+f"(c[0]), "+f"(c[1]), "+f"(c[2]), "+f"(c[3])
                 : "r"(a[0]), "r"(a[1]), "r"(a[2]), "r"(a[3]), "r"(b0), "r"(b1));
}

// exact 3-term bf16 split of an fp32 value
__device__ __forceinline__ void split3(float x, unsigned short& s0,
                                       unsigned short& s1, unsigned short& s2) {
    __nv_bfloat16 q0 = __float2bfloat16_rn(x);
    float r1 = x - __bfloat162float(q0);
    __nv_bfloat16 q1 = __float2bfloat16_rn(r1);
    float r2 = r1 - __bfloat162float(q1);
    __nv_bfloat16 q2 = __float2bfloat16_rn(r2);
    s0 = __bfloat16_as_ushort(q0);
    s1 = __bfloat16_as_ushort(q1);
    s2 = __bfloat16_as_ushort(q2);
}

// Persistent scratch
__device__ float g_A[NN * DIM];
__device__ float g_B[NN * DIM];
// w2^T bf16 split images: 3 x [n=128 rows][stride 136 bf16]
#define BROW   136
#define BSPLIT (128 * BROW)
__device__ __align__(16) unsigned short g_w2img[3 * BSPLIT];

// ---------------------------------------------------------------------------
// Kernel 0: build w2 split images once
// ---------------------------------------------------------------------------
__global__ void w2_split_kernel(const float* __restrict__ w2) {
    const int tid = threadIdx.x;
    for (int idx = tid; idx < 128 * 128; idx += 256) {
        int k = idx >> 7, j = idx & 127;
        unsigned short s0, s1, s2;
        split3(w2[idx], s0, s1, s2);
        g_w2img[0 * BSPLIT + j * BROW + k] = s0;
        g_w2img[1 * BSPLIT + j * BROW + k] = s1;
        g_w2img[2 * BSPLIT + j * BROW + k] = s2;
    }
}

// ---------------------------------------------------------------------------
// Kernel 1: AB = features @ [w1_top | w1_bot]  (proven)
// ---------------------------------------------------------------------------
#define K1_SMEM_FLOATS (64 * 132 + 128 * 68)

__global__ void layer1_gemm_kernel(const float* __restrict__ feat,
                                   const float* __restrict__ w1) {
    extern __shared__ float smem1[];
    float* featS = smem1;
    float* wS    = smem1 + 64 * 132;

    const int tid = threadIdx.x;
    const int m0 = blockIdx.x * 64;
    const int n0 = blockIdx.y * 64;

    for (int t = tid; t < 64 * 32; t += 256) {
        int r = t >> 5, c4 = (t & 31) << 2;
        int gr = m0 + r;
        float4 v = make_float4(0.f, 0.f, 0.f, 0.f);
        if (gr < NN) v = *(const float4*)&feat[gr * DIM + c4];
        *(float4*)&featS[r * 132 + c4] = v;
    }
    for (int t = tid; t < 128 * 16; t += 256) {
        int k = t >> 4, c4 = (t & 15) << 2;
        int n = n0 + c4;
        const float* src = (n < 128) ? &w1[k * 128 + n]
                                     : &w1[(128 + k) * 128 + (n - 128)];
        *(float4*)&wS[k * 68 + c4] = *(const float4*)src;
    }
    __syncthreads();

    const int ty = tid >> 4, tx = tid & 15;
    const int r0 = ty * 4, c0 = tx * 4;
    float acc[4][4];
#pragma unroll
    for (int i = 0; i < 4; ++i)
#pragma unroll
        for (int j = 0; j < 4; ++j) acc[i][j] = 0.f;

#pragma unroll 4
    for (int k = 0; k < 128; ++k) {
        float a[4];
#pragma unroll
        for (int i = 0; i < 4; ++i) a[i] = featS[(r0 + i) * 132 + k];
        float4 bq = *(const float4*)&wS[k * 68 + c0];
        float b[4] = {bq.x, bq.y, bq.z, bq.w};
#pragma unroll
        for (int i = 0; i < 4; ++i)
#pragma unroll
            for (int j = 0; j < 4; ++j) acc[i][j] = fmaf(a[i], b[j], acc[i][j]);
    }
#pragma unroll
    for (int i = 0; i < 4; ++i) {
        int node = m0 + r0 + i;
        if (node >= NN) continue;
        int n = n0 + c0;
        float4 o = make_float4(acc[i][0], acc[i][1], acc[i][2], acc[i][3]);
        if (n < 128) *(float4*)&g_A[node * DIM + n] = o;
        else         *(float4*)&g_B[node * DIM + (n - 128)] = o;
    }
}

// ---------------------------------------------------------------------------
// Kernel 2: 128 edges / block, 256 threads, mma.sync bf16 8-pass split GEMM,
//           passes ordered ASCENDING magnitude (Ozaki-style) so small terms
//           are not rounded away against O(1) accumulators.
#define OFF_B2   0
#define OFF_W3   512
#define OFF_B1   1024
#define OFF_W1R  1536
#define OFF_VALS 2048
#define OFF_COLS 2560
#define OFF_ZZ   3072
#define OFF_ZRED 3584
#define OFF_A    4608
#define ASPLIT   (128 * 272)
#define OFF_BM   (OFF_A + 3 * ASPLIT)
#define K2_SMEM  (OFF_BM + 3 * ASPLIT)      // 213504

// single (a-split, b-split) pass over K=128
__device__ __forceinline__ void gemm_pass(uint32_t aB, uint32_t bB,
                                          float (&acc)[2][8][4]) {
#pragma unroll
    for (int ks = 0; ks < 8; ++ks) {
        const uint32_t ko = ks * 32;
        uint32_t a0[4], a1[4];
        ldsm_x4(a0, aB + ko);
        ldsm_x4(a1, aB + 16 * 272 + ko);
#pragma unroll
        for (int q = 0; q < 4; ++q) {
            uint32_t b[4];
            ldsm_x4(b, bB + q * (16 * 272) + ko);
            mma16816(acc[0][2 * q],     a0, b[0], b[2]);
            mma16816(acc[0][2 * q + 1], a0, b[1], b[3]);
            mma16816(acc[1][2 * q],     a1, b[0], b[2]);
            mma16816(acc[1][2 * q + 1], a1, b[1], b[3]);
        }
    }
}

__global__ void __launch_bounds__(256, 1)
edge_mlp_mma_kernel(const int* __restrict__ colIdx,
                    const float* __restrict__ values,
                    const float* __restrict__ temperature,
                    const float* __restrict__ b1,
                    const float* __restrict__ w1,
                    const float* __restrict__ b2,
                    const float* __restrict__ w3,
                    const float* __restrict__ b3,
                    float* __restrict__ out) {
    extern __shared__ char smem[];
    const uint32_t sb = smem_to_u32(smem);
    float* b2s  = (float*)(smem + OFF_B2);
    float* w3s  = (float*)(smem + OFF_W3);
    float* b1s  = (float*)(smem + OFF_B1);
    float* w1rs = (float*)(smem + OFF_W1R);
    float* vals = (float*)(smem + OFF_VALS);
    int*   cols = (int*)  (smem + OFF_COLS);
    float* zz   = (float*)(smem + OFF_ZZ);
    float* zred = (float*)(smem + OFF_ZRED);

    const int tid  = threadIdx.x;
    const int wid  = tid >> 5;
    const int lane = tid & 31;
    const int e0 = blockIdx.x * 128;
    const int bn = blockIdx.x * 8;

    if (tid < 128) {
        b2s[tid]  = b2[tid];
        w3s[tid]  = w3[tid];
        b1s[tid]  = b1[tid];
        w1rs[tid] = w1[256 * 128 + tid];
    } else {
        int t = tid - 128;
        cols[t] = colIdx[e0 + t];
        vals[t] = values[e0 + t];
    }
    __syncthreads();

    // copy precomputed w2 split images into smem
    {
        const uint4* src = (const uint4*)g_w2img;
        uint4* dst = (uint4*)(smem + OFF_BM);
        for (int i = tid; i < (3 * ASPLIT) / 16; i += 256) dst[i] = src[i];
    }

    // ---- Phase 1: h1 (fp32, regs) -> 3 bf16 A-splits in smem ----
    {
        const int jj   = tid & 63;
        const int quad = tid >> 6;
        const float2 b1p = make_float2(b1s[2 * jj], b1s[2 * jj + 1]);
        const float2 w1p = make_float2(w1rs[2 * jj], w1rs[2 * jj + 1]);
#pragma unroll
        for (int nn = 0; nn < 2; ++nn) {
            const int node = quad * 2 + nn;
            float2 aA = *(const float2*)&g_A[(bn + node) * DIM + 2 * jj];
            aA.x += b1p.x; aA.y += b1p.y;
#pragma unroll
            for (int e = 0; e < 16; ++e) {
                const int el = node * 16 + e;
                const int c  = cols[el];
                const float v = vals[el];
                float2 gb = *(const float2*)&g_B[c * DIM + 2 * jj];
                float hx = fmaxf(fmaf(v, w1p.x, aA.x + gb.x), 0.f);
                float hy = fmaxf(fmaf(v, w1p.y, aA.y + gb.y), 0.f);
                unsigned short x0, x1, x2, y0, y1, y2;
                split3(hx, x0, x1, x2);
                split3(hy, y0, y1, y2);
                const uint32_t base = el * 272 + jj * 4;
                *(uint32_t*)(smem + OFF_A + 0 * ASPLIT + base) = (uint32_t)x0 | ((uint32_t)y0 << 16);
                *(uint32_t*)(smem + OFF_A + 1 * ASPLIT + base) = (uint32_t)x1 | ((uint32_t)y1 << 16);
                *(uint32_t*)(smem + OFF_A + 2 * ASPLIT + base) = (uint32_t)x2 | ((uint32_t)y2 << 16);
            }
        }
    }
    __syncthreads();

    // ---- Phase 2: mma.sync GEMM, warp tile M=32 x N=64 ----
    {
        const int mg = wid >> 1, nh = wid & 1;
        const int m0 = mg * 32, n0 = nh * 64;

        uint32_t aAddr[3], bAddr[3];
#pragma unroll
        for (int s = 0; s < 3; ++s) {
            aAddr[s] = sb + OFF_A  + s * ASPLIT + (m0 + (lane & 15)) * 272 + ((lane >> 4) << 4);
            bAddr[s] = sb + OFF_BM + s * ASPLIT + (n0 + (lane & 15)) * 272 + ((lane >> 4) << 4);
        }

        float acc[2][8][4];
#pragma unroll
        for (int st = 0; st < 2; ++st)
#pragma unroll
            for (int nt = 0; nt < 8; ++nt)
#pragma unroll
                for (int r = 0; r < 4; ++r) acc[st][nt][r] = 0.f;

        // Ascending-magnitude pass order (adjacent same-a passes reuse A frags):
        //  2^-27: a1b2, a2b1 ; 2^-18: a2b0, a1b1, a0b2 ; 2^-9: a0b1, a1b0 ; 1: a0b0
        gemm_pass(aAddr[1], bAddr[2], acc);
        gemm_pass(aAddr[2], bAddr[1], acc);
        gemm_pass(aAddr[2], bAddr[0], acc);
        gemm_pass(aAddr[1], bAddr[1], acc);
        gemm_pass(aAddr[0], bAddr[2], acc);
        gemm_pass(aAddr[0], bAddr[1], acc);
        gemm_pass(aAddr[1], bAddr[0], acc);
        gemm_pass(aAddr[0], bAddr[0], acc);

        // epilogue: +b2, relu, *w3, reduce over this warp's 64 cols
        const int g = lane >> 2, t4 = lane & 3;
        float zr[2][2] = {{0.f, 0.f}, {0.f, 0.f}};
#pragma unroll
        for (int st = 0; st < 2; ++st) {
#pragma unroll
            for (int nt = 0; nt < 8; ++nt) {
                const int c0 = n0 + nt * 8 + t4 * 2;
                const int c1 = c0 + 1;
                zr[st][0] = fmaf(fmaxf(acc[st][nt][0] + b2s[c0], 0.f), w3s[c0], zr[st][0]);
                zr[st][0] = fmaf(fmaxf(acc[st][nt][1] + b2s[c1], 0.f), w3s[c1], zr[st][0]);
                zr[st][1] = fmaf(fmaxf(acc[st][nt][2] + b2s[c0], 0.f), w3s[c0], zr[st][1]);
                zr[st][1] = fmaf(fmaxf(acc[st][nt][3] + b2s[c1], 0.f), w3s[c1], zr[st][1]);
            }
        }
        const unsigned FULL = 0xffffffffu;
#pragma unroll
        for (int st = 0; st < 2; ++st)
#pragma unroll
            for (int h = 0; h < 2; ++h) {
                float v = zr[st][h];
                v += __shfl_down_sync(FULL, v, 2);
                v += __shfl_down_sync(FULL, v, 1);
                zr[st][h] = v;
            }
        if (t4 == 0) {
#pragma unroll
            for (int st = 0; st < 2; ++st) {
                zred[(m0 + st * 16 + g) * 2 + nh]     = zr[st][0];
                zred[(m0 + st * 16 + g + 8) * 2 + nh] = zr[st][1];
            }
        }
    }
    __syncthreads();

    if (tid < 128)
        zz[tid] = (zred[2 * tid] + zred[2 * tid + 1]) + b3[0];
    __syncthreads();

    // ---- Phase 3: proven exact chain (warp w -> node w) ----
    {
        const unsigned FULL = 0xffffffffu;
        const int l = lane & 15;
        const int el = wid * 16 + l;
        const float zv = zz[el];

        float m = zv;
#pragma unroll
        for (int o = 8; o >= 1; o >>= 1) m = fmaxf(m, __shfl_xor_sync(FULL, m, o, 16));
        float x1 = __fsub_rn(zv, m);
        float ev = (float)exp((double)x1);
        float s = 0.f;
#pragma unroll
        for (int o = 0; o < 16; ++o) s = __fadd_rn(s, __shfl_sync(FULL, ev, o, 16));
        float pi = __fdiv_rn(ev, s);

        float larg = __fadd_rn(pi, 1e-8f);
        float lg = (float)log((double)larg);
        float sx = __fdiv_rn(lg, temperature[0]);
        float hard = (float)(1.0 / (1.0 + exp(-(double)sx)));
        hard = fminf(fmaxf(hard, 0.f), 1.f);

        float m2 = hard;
#pragma unroll
        for (int o = 8; o >= 1; o >>= 1) m2 = fmaxf(m2, __shfl_xor_sync(FULL, m2, o, 16));
        float x2 = __fsub_rn(hard, m2);
        float e2 = (float)exp((double)x2);
        float s2 = 0.f;
#pragma unroll
        for (int o = 0; o < 16; ++o) s2 = __fadd_rn(s2, __shfl_sync(FULL, e2, o, 16));
        float y = __fdiv_rn(e2, s2);

        int r = 0;
#pragma unroll
        for (int o = 0; o < 16; ++o) {
            float yo = __shfl_sync(FULL, y, o, 16);
            r += (yo > y) || (yo == y && o < l);
        }
        unsigned bal = __ballot_sync(FULL, (r == 7) && (lane < 16));
        int src = __ffs(bal) - 1;
        float thre = __shfl_sync(FULL, y, src);

        float t = __fadd_rn(__fsub_rn(y, thre), 1e-7f);
        float outv = (t > 0.f) ? y : 0.f;
        if (lane < 16) out[e0 + el] = outv;
    }
}

// ---------------------------------------------------------------------------
extern "C" void kernel_launch(void* const* d_in, const int* in_sizes, int n_in,
                              void* d_out, int out_size) {
    const float* feat        = (const float*)d_in[0];
    const int*   indices     = (const int*)d_in[1];
    const float* values      = (const float*)d_in[2];
    const float* temperature = (const float*)d_in[3];
    const float* w1          = (const float*)d_in[4];
    const float* b1          = (const float*)d_in[5];
    const float* w2          = (const float*)d_in[6];
    const float* b2          = (const float*)d_in[7];
    const float* w3          = (const float*)d_in[8];
    const float* b3          = (const float*)d_in[9];
    float* out = (float*)d_out;

    const int* colIdx = indices + EDGES;

    const size_t smem1 = K1_SMEM_FLOATS * sizeof(float);
    cudaFuncSetAttribute(layer1_gemm_kernel,
                         cudaFuncAttributeMaxDynamicSharedMemorySize, (int)smem1);
    cudaFuncSetAttribute(edge_mlp_mma_kernel,
                         cudaFuncAttributeMaxDynamicSharedMemorySize, K2_SMEM);

    w2_split_kernel<<<1, 256>>>(w2);

    dim3 g1((NN + 63) / 64, 2 * DIM / 64);
    layer1_gemm_kernel<<<g1, 256, smem1>>>(feat, w1);

    edge_mlp_mma_kernel<<<EDGES / 128, 256, K2_SMEM>>>(
        colIdx, values, temperature, b1, w1, b2, w3, b3, out);
}

// round 10
// speedup vs baseline: 1.5211x; 1.5211x over previous
#include <cuda_runtime.h>
#include <cuda_bf16.h>
#include <math.h>

// Problem constants (fixed by the dataset)
#define NN    50000
#define DEG   16
#define EDGES (NN * DEG)      // 800000
#define DIM   128
#define HID   128

#define NPB   16              // nodes per block (kernel 2)
#define EPB   256             // edges per block
#define K2T   512             // threads (kernel 2)
#define H1SR  260             // h1T row stride (floats), multiple of 4

typedef unsigned long long ull;

#define FMA_F32X2(acc, a, b) \
    asm("fma.rn.f32x2 %0, %1, %2, %0;" : "+l"(acc) : "l"(a), "l"(b))
#define PACK_F32X2(out, lo, hi) \
    asm("mov.b64 %0, {%1, %2};" : "=l"(out) : "r"(lo), "r"(hi))
#define UNPACK_F32X2(lo, hi, in) \
    asm("mov.b64 {%0, %1}, %2;" : "=r"(lo), "=r"(hi) : "l"(in))

// Persistent scratch: layer-1 node projections A = F @ W1[0:128], B = F @ W1[128:256]
__device__ float g_A[NN * DIM];
__device__ float g_B[NN * DIM];

// ---------------------------------------------------------------------------
// Kernel 1: AB = features[N,128] @ Wcat[128,256]. Tiled fp32 GEMM. (proven)
// ---------------------------------------------------------------------------
#define K1_SMEM_FLOATS (64 * 132 + 128 * 68)

__global__ void layer1_gemm_kernel(const float* __restrict__ feat,
                                   const float* __restrict__ w1) {
    extern __shared__ float smem1[];
    float* featS = smem1;              // [64][132]
    float* wS    = smem1 + 64 * 132;   // [128][68]

    const int tid = threadIdx.x;
    const int m0 = blockIdx.x * 64;
    const int n0 = blockIdx.y * 64;

    for (int t = tid; t < 64 * 32; t += 256) {
        int r = t >> 5, c4 = (t & 31) << 2;
        int gr = m0 + r;
        float4 v = make_float4(0.f, 0.f, 0.f, 0.f);
        if (gr < NN) v = *(const float4*)&feat[gr * DIM + c4];
        *(float4*)&featS[r * 132 + c4] = v;
    }
    for (int t = tid; t < 128 * 16; t += 256) {
        int k = t >> 4, c4 = (t & 15) << 2;
        int n = n0 + c4;
        const float* src = (n < 128) ? &w1[k * 128 + n]
                                     : &w1[(128 + k) * 128 + (n - 128)];
        *(float4*)&wS[k * 68 + c4] = *(const float4*)src;
    }
    __syncthreads();

    const int ty = tid >> 4, tx = tid & 15;
    const int r0 = ty * 4, c0 = tx * 4;
    float acc[4][4];
#pragma unroll
    for (int i = 0; i < 4; ++i)
#pragma unroll
        for (int j = 0; j < 4; ++j) acc[i][j] = 0.f;

#pragma unroll 4
    for (int k = 0; k < 128; ++k) {
        float a[4];
#pragma unroll
        for (int i = 0; i < 4; ++i) a[i] = featS[(r0 + i) * 132 + k];
        float4 bq = *(const float4*)&wS[k * 68 + c0];
        float b[4] = {bq.x, bq.y, bq.z, bq.w};
#pragma unroll
        for (int i = 0; i < 4; ++i)
#pragma unroll
            for (int j = 0; j < 4; ++j) acc[i][j] = fmaf(a[i], b[j], acc[i][j]);
    }

#pragma unroll
    for (int i = 0; i < 4; ++i) {
        int node = m0 + r0 + i;
        if (node >= NN) continue;
        int n = n0 + c0;
        float4 o = make_float4(acc[i][0], acc[i][1], acc[i][2], acc[i][3]);
        if (n < 128) *(float4*)&g_A[node * DIM + n] = o;
        else         *(float4*)&g_B[node * DIM + (n - 128)] = o;
    }
}

// ---------------------------------------------------------------------------
// Kernel 2: per block = 16 nodes = 256 edges, 512 threads.
//  Phase 1: h1T[j][el] = relu(A[row]+B[col]+v*w1[256,j]+b1[j])  (coalesced)
//  Phase 2: packed f32x2 FMAs, software-pipelined (a prefetched 1 iter ahead)
//  Phase 3: per-node softmax -> hard-concrete -> softmax -> top-8 mask.
// ---------------------------------------------------------------------------
#define K2_SMEM_FLOATS (128 * H1SR + 128 * 128 + EPB * 9 + 4 * 128 + 3 * EPB)

__global__ void __launch_bounds__(K2T, 1)
edge_mlp_mask_kernel(const int* __restrict__ colIdx,
                     const float* __restrict__ values,
                     const float* __restrict__ temperature,
                     const float* __restrict__ w1,
                     const float* __restrict__ b1,
                     const float* __restrict__ w2,
                     const float* __restrict__ b2,
                     const float* __restrict__ w3,
                     const float* __restrict__ b3,
                     float* __restrict__ out) {
    extern __shared__ float smem[];
    float* h1T   = smem;                      // [128(j)][260]
    float* w2s   = h1T + 128 * H1SR;          // [128(k)][128(j)]
    float* zred  = w2s + 128 * 128;           // [256(el)][9]   (also k=128 spill pad)
    float* b2s   = zred + EPB * 9;            // [128]
    float* w3s   = b2s + 128;                 // [128]
    float* b1s   = w3s + 128;                 // [128]
    float* w1rs  = b1s + 128;                 // [128]
    float* vals  = w1rs + 128;                // [256]
    float* zz    = vals + EPB;                // [256]
    int*   cols  = (int*)(zz + EPB);          // [256]

    const int tid = threadIdx.x;
    const int base_node = blockIdx.x * NPB;
    const int e0 = blockIdx.x * EPB;

    // ---- stage w2, b1/b2/w3, w1 value-row, colIdx, values ----
    for (int t = tid; t < 128 * 32; t += K2T) {
        int k = t >> 5, c4 = (t & 31) << 2;
        *(float4*)&w2s[k * 128 + c4] = *(const float4*)&w2[k * 128 + c4];
    }
    if (tid < 128) {
        b2s[tid]  = b2[tid];
        w3s[tid]  = w3[tid];
        b1s[tid]  = b1[tid];
        w1rs[tid] = w1[256 * 128 + tid];
    }
    {
        int t2 = tid - 128;
        if (t2 >= 0 && t2 < EPB) {
            cols[t2] = colIdx[e0 + t2];
            vals[t2] = values[e0 + t2];
        }
    }
    __syncthreads();

    // ---- Phase 1: j across lanes (coalesced g_B rows), float4 edge-quads ----
    {
        const int j = tid & 127;                 // feature, consecutive in warp
        const int g = tid >> 7;                  // 0..3 -> 64-edge group
        const float b1j = b1s[j];
        const float wrj = w1rs[j];
#pragma unroll
        for (int nn = 0; nn < 4; ++nn) {         // node within group
            const int node = g * 4 + nn;
            const float a = g_A[(base_node + node) * DIM + j] + b1j;
#pragma unroll
            for (int q = 0; q < 4; ++q) {        // edge quad within node
                const int el = node * 16 + q * 4;
                int4   c4 = *(const int4*)&cols[el];
                float4 v4 = *(const float4*)&vals[el];
                float4 h;
                h.x = fmaf(v4.x, wrj, a + g_B[c4.x * DIM + j]);
                h.y = fmaf(v4.y, wrj, a + g_B[c4.y * DIM + j]);
                h.z = fmaf(v4.z, wrj, a + g_B[c4.z * DIM + j]);
                h.w = fmaf(v4.w, wrj, a + g_B[c4.w * DIM + j]);
                h.x = fmaxf(h.x, 0.f); h.y = fmaxf(h.y, 0.f);
                h.z = fmaxf(h.z, 0.f); h.w = fmaxf(h.w, 0.f);
                h1T[j * H1SR + el + 0] = h.x;
                h1T[j * H1SR + el + 1] = h.y;
                h1T[j * H1SR + el + 2] = h.z;
                h1T[j * H1SR + el + 3] = h.w;
            }
        }
    }
    __syncthreads();

    // ---- Phase 2: packed f32x2 GEMM, software-pipelined over k ----
    {
        const int w    = tid >> 5;        // warp 0..15
        const int lane = tid & 31;
        const int eh   = w >> 3;          // edge half (0/1)
        const int grp  = w & 7;           // col group (0..7)
        const int er0  = eh * 128 + lane * 4;   // 4 consecutive edges
        const int jc0  = grp * 16;              // 16 cols = 8 col-pairs

        ull acc[4][8];
#pragma unroll
        for (int i = 0; i < 4; ++i)
#pragma unroll
            for (int p = 0; p < 8; ++p) acc[i][p] = 0ull;

        // prologue: a for k=0
        float4 a_c = *(const float4*)&h1T[er0];

#pragma unroll 2
        for (int k = 0; k < 128; ++k) {
            // prefetch a for k+1 (k=127 reads row 128 -> lands in w2s, unused)
            float4 a_n = *(const float4*)&h1T[(k + 1) * H1SR + er0];

            // b: 8 col-pairs, warp-uniform broadcast (k=... always valid;
            // row 128 would land in zred pad, but k stops at 127 for b)
            const ulonglong2* wp = (const ulonglong2*)&w2s[k * 128 + jc0];
            ulonglong2 b01 = wp[0], b23 = wp[1], b45 = wp[2], b67 = wp[3];

            ull pa[4];
            PACK_F32X2(pa[0], __float_as_uint(a_c.x), __float_as_uint(a_c.x));
            PACK_F32X2(pa[1], __float_as_uint(a_c.y), __float_as_uint(a_c.y));
            PACK_F32X2(pa[2], __float_as_uint(a_c.z), __float_as_uint(a_c.z));
            PACK_F32X2(pa[3], __float_as_uint(a_c.w), __float_as_uint(a_c.w));

            ull pb[8];
            pb[0] = b01.x; pb[1] = b01.y;
            pb[2] = b23.x; pb[3] = b23.y;
            pb[4] = b45.x; pb[5] = b45.y;
            pb[6] = b67.x; pb[7] = b67.y;
#pragma unroll
            for (int i = 0; i < 4; ++i)
#pragma unroll
                for (int p = 0; p < 8; ++p)
                    FMA_F32X2(acc[i][p], pa[i], pb[p]);

            a_c = a_n;   // rotate
        }

        // epilogue: unpack, +b2, relu, w3 partial dot (col-ascending order)
#pragma unroll
        for (int i = 0; i < 4; ++i) {
            float s = 0.f;
#pragma unroll
            for (int p = 0; p < 8; ++p) {
                unsigned lo, hi;
                UNPACK_F32X2(lo, hi, acc[i][p]);
                float h2a = fmaxf(__uint_as_float(lo) + b2s[jc0 + 2 * p], 0.f);
                s = fmaf(h2a, w3s[jc0 + 2 * p], s);
                float h2b = fmaxf(__uint_as_float(hi) + b2s[jc0 + 2 * p + 1], 0.f);
                s = fmaf(h2b, w3s[jc0 + 2 * p + 1], s);
            }
            zred[(er0 + i) * 9 + grp] = s;
        }
    }
    __syncthreads();

    if (tid < EPB) {
        float s = b3[0];
#pragma unroll
        for (int g = 0; g < 8; ++g) s += zred[tid * 9 + g];
        zz[tid] = s;
    }
    __syncthreads();

    // ---- Phase 3: per-node (warp -> node) exact softmax chain + top-8 mask ----
    {
        const unsigned FULL = 0xffffffffu;
        const int lane = tid & 31;
        const int l = lane & 15;
        const int wnode = tid >> 5;          // 0..15
        const int el = wnode * 16 + l;
        const float zv = zz[el];

        float m = zv;
#pragma unroll
        for (int o = 8; o >= 1; o >>= 1) m = fmaxf(m, __shfl_xor_sync(FULL, m, o, 16));
        float x1 = __fsub_rn(zv, m);
        float ev = (float)exp((double)x1);
        float s = 0.f;
#pragma unroll
        for (int o = 0; o < 16; ++o) s = __fadd_rn(s, __shfl_sync(FULL, ev, o, 16));
        float pi = __fdiv_rn(ev, s);

        float larg = __fadd_rn(pi, 1e-8f);
        float lg = (float)log((double)larg);
        float sx = __fdiv_rn(lg, temperature[0]);
        float hard = (float)(1.0 / (1.0 + exp(-(double)sx)));
        hard = fminf(fmaxf(hard, 0.f), 1.f);

        float m2 = hard;
#pragma unroll
        for (int o = 8; o >= 1; o >>= 1) m2 = fmaxf(m2, __shfl_xor_sync(FULL, m2, o, 16));
        float x2 = __fsub_rn(hard, m2);
        float e2 = (float)exp((double)x2);
        float s2 = 0.f;
#pragma unroll
        for (int o = 0; o < 16; ++o) s2 = __fadd_rn(s2, __shfl_sync(FULL, e2, o, 16));
        float y = __fdiv_rn(e2, s2);

        int r = 0;
#pragma unroll
        for (int o = 0; o < 16; ++o) {
            float yo = __shfl_sync(FULL, y, o, 16);
            r += (yo > y) || (yo == y && o < l);
        }
        unsigned bal = __ballot_sync(FULL, (r == 7) && (lane < 16));
        int src = __ffs(bal) - 1;
        float thre = __shfl_sync(FULL, y, src);

        float t = __fadd_rn(__fsub_rn(y, thre), 1e-7f);
        float outv = (t > 0.f) ? y : 0.f;
        if (lane < 16) out[e0 + el] = outv;
    }
}

// ---------------------------------------------------------------------------
extern "C" void kernel_launch(void* const* d_in, const int* in_sizes, int n_in,
                              void* d_out, int out_size) {
    const float* feat        = (const float*)d_in[0];
    const int*   indices     = (const int*)d_in[1];   // [2, E]
    const float* values      = (const float*)d_in[2]; // [E, 1]
    const float* temperature = (const float*)d_in[3];
    const float* w1          = (const float*)d_in[4]; // [257, 128]
    const float* b1          = (const float*)d_in[5];
    const float* w2          = (const float*)d_in[6]; // [128, 128]
    const float* b2          = (const float*)d_in[7];
    const float* w3          = (const float*)d_in[8]; // [128, 1]
    const float* b3          = (const float*)d_in[9];
    float* out = (float*)d_out;

    const int* colIdx = indices + EDGES;  // indices[1]

    const size_t smem1 = K1_SMEM_FLOATS * sizeof(float);
    const size_t smem2 = K2_SMEM_FLOATS * sizeof(float);
    cudaFuncSetAttribute(layer1_gemm_kernel,
                         cudaFuncAttributeMaxDynamicSharedMemorySize, (int)smem1);
    cudaFuncSetAttribute(edge_mlp_mask_kernel,
                         cudaFuncAttributeMaxDynamicSharedMemorySize, (int)smem2);

    dim3 g1((NN + 63) / 64, 2 * DIM / 64);  // 782 x 4
    layer1_gemm_kernel<<<g1, 256, smem1>>>(feat, w1);

    edge_mlp_mask_kernel<<<EDGES / EPB, K2T, smem2>>>(
        colIdx, values, temperature, w1, b1, w2, b2, w3, b3, out);
}